// round 7
// baseline (speedup 1.0000x reference)
#include <cuda_runtime.h>
#include <math.h>

#define NB   256
#define DD   2048
#define II   5504
#define KSEL 128

// ---------------- scratch (device globals) ----------------------------------
__device__ float g_scores[NB];
__device__ int   g_sel[KSEL];
__device__ float g_x [KSEL*DD];     // gathered selected rows (residual)
__device__ float g_x2[KSEL*DD];     // post-attention residual
__device__ float g_h [KSEL*DD];     // rms(x)        (GEMM A)
__device__ float g_v [KSEL*DD];     // h@wv+bv       (GEMM A)
__device__ float g_h2[KSEL*DD];     // rms(x2)       (GEMM A)
__device__ float g_a [KSEL*II];     // silu(g)*u     (GEMM A)
#define SBELEMS (16*KSEL*DD)        // 16 splits x 128 x 2048 (>= 4*128*5504)
__device__ float g_sb0[SBELEMS];
__device__ float g_sb1[SBELEMS];

// ---------------- router scores ---------------------------------------------
__global__ __launch_bounds__(256) void scores_kernel(
    const float* __restrict__ hs, const float* __restrict__ rw,
    const float* __restrict__ rb)
{
    int b = blockIdx.x;
    const float4* row = (const float4*)(hs + (size_t)b * DD);
    const float4* w4  = (const float4*)rw;
    float s = 0.f;
    #pragma unroll
    for (int j = 0; j < 2; j++) {
        int i = j * 256 + threadIdx.x;
        float4 v = row[i], w = w4[i];
        s += v.x * w.x + v.y * w.y + v.z * w.z + v.w * w.w;
    }
    __shared__ float sm[256];
    sm[threadIdx.x] = s; __syncthreads();
    for (int st = 128; st > 0; st >>= 1) {
        if (threadIdx.x < st) sm[threadIdx.x] += sm[threadIdx.x + st];
        __syncthreads();
    }
    if (threadIdx.x == 0) g_scores[b] = sm[0] + rb[0];
}

// ---------------- top-k selection -------------------------------------------
__global__ __launch_bounds__(256) void topk_kernel()
{
    __shared__ float s[NB];
    __shared__ int   flag[NB];
    int t = threadIdx.x;
    s[t] = g_scores[t];
    __syncthreads();
    float mine = s[t];
    int rank = 0;
    for (int j = 0; j < NB; j++) {
        float o = s[j];
        if (o > mine || (o == mine && j < t)) rank++;
    }
    flag[t] = (rank < KSEL) ? 1 : 0;
    __syncthreads();
    if (t == 0) {
        int c = 0;
        for (int j = 0; j < NB; j++) if (flag[j]) g_sel[c++] = j;
    }
}

// ---------------- passthrough copy ------------------------------------------
__global__ __launch_bounds__(256) void copy_kernel(
    const float4* __restrict__ src, float4* __restrict__ dst, int n4)
{
    for (int i = blockIdx.x * blockDim.x + threadIdx.x; i < n4;
         i += gridDim.x * blockDim.x)
        dst[i] = src[i];
}

// ---------------- gather + RMSNorm (fp32 out) -------------------------------
__global__ __launch_bounds__(512) void gather_rms_kernel(
    const float* __restrict__ src_full, const float* __restrict__ w,
    float* __restrict__ x_out, float* __restrict__ h_out, int gather)
{
    int r = blockIdx.x;
    int t = threadIdx.x;
    const float* src = gather ? (src_full + (size_t)g_sel[r] * DD)
                              : (src_full + (size_t)r * DD);
    float4 v = ((const float4*)src)[t];
    float ss = v.x * v.x + v.y * v.y + v.z * v.z + v.w * v.w;
    __shared__ float sm[512];
    sm[t] = ss; __syncthreads();
    for (int st = 256; st > 0; st >>= 1) {
        if (t < st) sm[t] += sm[t + st];
        __syncthreads();
    }
    float inv = rsqrtf(sm[0] * (1.0f / (float)DD) + 1e-6f);
    if (x_out) ((float4*)(x_out + (size_t)r * DD))[t] = v;
    float4 wv = ((const float4*)w)[t];
    ((float4*)(h_out + (size_t)r * DD))[t] =
        make_float4(v.x * inv * wv.x, v.y * inv * wv.y,
                    v.z * inv * wv.z, v.w * inv * wv.w);
}

// ---------------- tf32 mma helpers ------------------------------------------
__device__ __forceinline__ unsigned f2tf(float f) {
    unsigned u;
    asm("cvt.rna.tf32.f32 %0, %1;" : "=r"(u) : "f"(f));
    return u;
}
__device__ __forceinline__ void mma_tf32(float* c, const unsigned* a,
                                         const unsigned* b) {
    asm volatile("mma.sync.aligned.m16n8k8.row.col.f32.tf32.tf32.f32 "
                 "{%0,%1,%2,%3}, {%4,%5,%6,%7}, {%8,%9}, {%0,%1,%2,%3};"
                 : "+f"(c[0]), "+f"(c[1]), "+f"(c[2]), "+f"(c[3])
                 : "r"(a[0]), "r"(a[1]), "r"(a[2]), "r"(a[3]),
                   "r"(b[0]), "r"(b[1]));
}
#define CP_ASYNC16(dst, src) \
    asm volatile("cp.async.cg.shared.global [%0], [%1], 16;" \
                 :: "r"(dst), "l"(src))
#define CP_COMMIT()  asm volatile("cp.async.commit_group;")
#define CP_WAIT2()   asm volatile("cp.async.wait_group 2;")
#define CP_WAIT0()   asm volatile("cp.async.wait_group 0;")

// ---------------- TF32 GEMM: Csplit[z] = A[128,Kslice] @ W[Kslice,N] ---------
// A fp32 [128,K] row-major, W fp32 [K,N] row-major. cp.async 4-stage pipeline.
// grid = (N/128, splits, nW). 256 threads, 2 CTAs/SM.
// kPerSplit and K MUST be multiples of 16.
#define BK      16
#define A_PITCH 20                    // floats (16 data + 4 pad) -> conflict-free
#define B_PITCH 136                   // floats (128 data + 8 pad) -> conflict-free
#define A_STAGE (128*A_PITCH)         // floats
#define B_STAGE (BK*B_PITCH)          // floats
#define NSTAGE  4
#define SMEM_BYTES (NSTAGE*(A_STAGE+B_STAGE)*(int)sizeof(float))

__global__ __launch_bounds__(256, 2) void tgemm_kernel(
    const float* __restrict__ A,
    const float* __restrict__ W0, const float* __restrict__ W1,
    float* __restrict__ C0, float* __restrict__ C1,
    int N, int K, int kPerSplit)
{
    extern __shared__ float smf[];
    float* As = smf;
    float* Bs = smf + NSTAGE * A_STAGE;
    unsigned As_u = (unsigned)__cvta_generic_to_shared(As);
    unsigned Bs_u = (unsigned)__cvta_generic_to_shared(Bs);

    const float* W = blockIdx.z ? W1 : W0;
    float* C       = blockIdx.z ? C1 : C0;

    const int tid  = threadIdx.x;
    const int lane = tid & 31, warp = tid >> 5;
    const int wm = warp & 3, wn = warp >> 2;     // 4 M-warps x 2 N-warps
    const int n0 = blockIdx.x * 128;
    const int kb = blockIdx.y * kPerSplit;
    const int ke = min(kb + kPerSplit, K);
    const int nch = (ke - kb) >> 4;              // 16-k chunks

    // copy mapping (2x 16B chunks each for A and B per thread)
    const int ar0 = tid >> 2,          ap0 = (tid & 3) << 2;        // A row, col
    const int ar1 = (tid + 256) >> 2,  ap1 = ap0;
    const int br0 = tid >> 5,          bp0 = (tid & 31) << 2;       // B row, col
    const int br1 = (tid + 256) >> 5,  bp1 = bp0;

    float acc[2][8][4];
    #pragma unroll
    for (int i = 0; i < 2; i++)
        #pragma unroll
        for (int j = 0; j < 8; j++)
            #pragma unroll
            for (int q = 0; q < 4; q++) acc[i][j][q] = 0.f;

    auto issue_copy = [&](int c) {
        int s = c & (NSTAGE - 1);
        int k0 = kb + c * BK;
        unsigned a_s = As_u + (s * A_STAGE) * 4;
        unsigned b_s = Bs_u + (s * B_STAGE) * 4;
        CP_ASYNC16(a_s + (ar0 * A_PITCH + ap0) * 4, A + (size_t)ar0 * K + k0 + ap0);
        CP_ASYNC16(a_s + (ar1 * A_PITCH + ap1) * 4, A + (size_t)ar1 * K + k0 + ap1);
        CP_ASYNC16(b_s + (br0 * B_PITCH + bp0) * 4, W + (size_t)(k0 + br0) * N + n0 + bp0);
        CP_ASYNC16(b_s + (br1 * B_PITCH + bp1) * 4, W + (size_t)(k0 + br1) * N + n0 + bp1);
    };

    auto mmastage = [&](int s) {
        const float* Ab = As + s * A_STAGE;
        const float* Bb = Bs + s * B_STAGE;
        #pragma unroll
        for (int ks = 0; ks < 2; ks++) {
            unsigned af[2][4];
            #pragma unroll
            for (int at = 0; at < 2; at++) {
                int r = wm * 32 + at * 16 + (lane >> 2);
                int c = ks * 8 + (lane & 3);
                af[at][0] = f2tf(Ab[r * A_PITCH + c]);
                af[at][1] = f2tf(Ab[(r + 8) * A_PITCH + c]);
                af[at][2] = f2tf(Ab[r * A_PITCH + c + 4]);
                af[at][3] = f2tf(Ab[(r + 8) * A_PITCH + c + 4]);
            }
            unsigned bf[8][2];
            #pragma unroll
            for (int nf = 0; nf < 8; nf++) {
                int kr = ks * 8 + (lane & 3);
                int nc = wn * 64 + nf * 8 + (lane >> 2);
                bf[nf][0] = f2tf(Bb[kr * B_PITCH + nc]);
                bf[nf][1] = f2tf(Bb[(kr + 4) * B_PITCH + nc]);
            }
            #pragma unroll
            for (int at = 0; at < 2; at++)
                #pragma unroll
                for (int nf = 0; nf < 8; nf++)
                    mma_tf32(acc[at][nf], af[at], bf[nf]);
        }
    };

    // prologue: 3 chunks in flight
    #pragma unroll
    for (int c = 0; c < NSTAGE - 1; c++) {
        if (c < nch) issue_copy(c);
        CP_COMMIT();
    }

    for (int c = 0; c < nch; c++) {
        CP_WAIT2();
        __syncthreads();
        if (c + NSTAGE - 1 < nch) issue_copy(c + NSTAGE - 1);
        CP_COMMIT();
        mmastage(c & (NSTAGE - 1));
    }
    CP_WAIT0();

    float* Cs = C + (size_t)blockIdx.y * 128 * N;
    int g = lane >> 2, q = lane & 3;
    #pragma unroll
    for (int at = 0; at < 2; at++) {
        int r = wm * 32 + at * 16 + g;
        #pragma unroll
        for (int nf = 0; nf < 8; nf++) {
            int cix = n0 + wn * 64 + nf * 8 + 2 * q;
            *(float2*)&Cs[(size_t)r * N + cix] =
                make_float2(acc[at][nf][0], acc[at][nf][1]);
            *(float2*)&Cs[(size_t)(r + 8) * N + cix] =
                make_float2(acc[at][nf][2], acc[at][nf][3]);
        }
    }
}

// ---------------- split-K reductions with fused epilogues --------------------
template<int SPLITS>
__global__ __launch_bounds__(256) void red_bias_kernel(
    const float* __restrict__ S, const float* __restrict__ bias,
    float* __restrict__ out, int N)
{
    int i = blockIdx.x * 256 + threadIdx.x;
    int tot = KSEL * N / 4;
    if (i >= tot) return;
    const float4* S4 = (const float4*)S;
    size_t stride = (size_t)KSEL * N / 4;
    float4 s = S4[i];
    #pragma unroll
    for (int z = 1; z < SPLITS; z++) {
        float4 t = S4[z * stride + i];
        s.x += t.x; s.y += t.y; s.z += t.z; s.w += t.w;
    }
    float4 b = ((const float4*)bias)[i % (N / 4)];
    s.x += b.x; s.y += b.y; s.z += b.z; s.w += b.w;
    ((float4*)out)[i] = s;
}

template<int SPLITS>
__global__ __launch_bounds__(256) void red_resid_kernel(
    const float* __restrict__ S, const float* __restrict__ X,
    float* __restrict__ out, int N)
{
    int i = blockIdx.x * 256 + threadIdx.x;
    int tot = KSEL * N / 4;
    if (i >= tot) return;
    const float4* S4 = (const float4*)S;
    size_t stride = (size_t)KSEL * N / 4;
    float4 s = S4[i];
    #pragma unroll
    for (int z = 1; z < SPLITS; z++) {
        float4 t = S4[z * stride + i];
        s.x += t.x; s.y += t.y; s.z += t.z; s.w += t.w;
    }
    float4 x = ((const float4*)X)[i];
    s.x += x.x; s.y += x.y; s.z += x.z; s.w += x.w;
    ((float4*)out)[i] = s;
}

template<int SPLITS>
__global__ __launch_bounds__(256) void red_silu_kernel(
    const float* __restrict__ Sg, const float* __restrict__ Su,
    float* __restrict__ out, int N)
{
    int i = blockIdx.x * 256 + threadIdx.x;
    int tot = KSEL * N / 4;
    if (i >= tot) return;
    const float4* G4 = (const float4*)Sg;
    const float4* U4 = (const float4*)Su;
    size_t stride = (size_t)KSEL * N / 4;
    float4 g = G4[i], u = U4[i];
    #pragma unroll
    for (int z = 1; z < SPLITS; z++) {
        float4 t = G4[z * stride + i];
        g.x += t.x; g.y += t.y; g.z += t.z; g.w += t.w;
        float4 v = U4[z * stride + i];
        u.x += v.x; u.y += v.y; u.z += v.z; u.w += v.w;
    }
    float4 o;
    o.x = g.x / (1.f + expf(-g.x)) * u.x;
    o.y = g.y / (1.f + expf(-g.y)) * u.y;
    o.z = g.z / (1.f + expf(-g.z)) * u.z;
    o.w = g.w / (1.f + expf(-g.w)) * u.w;
    ((float4*)out)[i] = o;
}

template<int SPLITS>
__global__ __launch_bounds__(256) void red_scatter_kernel(
    const float* __restrict__ S, const float* __restrict__ X2,
    float* __restrict__ out)   // out: [256][2048]
{
    int i = blockIdx.x * 256 + threadIdx.x;
    int tot = KSEL * DD / 4;
    if (i >= tot) return;
    const float4* S4 = (const float4*)S;
    size_t stride = (size_t)KSEL * DD / 4;
    float4 s = S4[i];
    #pragma unroll
    for (int z = 1; z < SPLITS; z++) {
        float4 t = S4[z * stride + i];
        s.x += t.x; s.y += t.y; s.z += t.z; s.w += t.w;
    }
    float4 x = ((const float4*)X2)[i];
    s.x += x.x; s.y += x.y; s.z += x.z; s.w += x.w;
    int row = i / (DD / 4), c4 = i % (DD / 4);
    ((float4*)out)[(size_t)g_sel[row] * (DD / 4) + c4] = s;
}

// ---------------- launch -----------------------------------------------------
extern "C" void kernel_launch(void* const* d_in, const int* in_sizes, int n_in,
                              void* d_out, int out_size)
{
    const float* hs  = (const float*)d_in[0];
    const float* rw  = (const float*)d_in[3];
    const float* rb  = (const float*)d_in[4];
    const float* ln1 = (const float*)d_in[5];
    const float* ln2 = (const float*)d_in[6];
    // wq/bq/wk/bk (d_in[7..10]) dead: softmax over a single key == 1 -> o == v
    const float* wv  = (const float*)d_in[11];
    const float* bv  = (const float*)d_in[12];
    const float* wo  = (const float*)d_in[13];
    const float* wg  = (const float*)d_in[14];
    const float* wu  = (const float*)d_in[15];
    const float* wd  = (const float*)d_in[16];
    float* out = (float*)d_out;

    float *px, *px2, *ph, *pv, *ph2, *pa, *psb0, *psb1;
    cudaGetSymbolAddress((void**)&px,   g_x);
    cudaGetSymbolAddress((void**)&px2,  g_x2);
    cudaGetSymbolAddress((void**)&ph,   g_h);
    cudaGetSymbolAddress((void**)&pv,   g_v);
    cudaGetSymbolAddress((void**)&ph2,  g_h2);
    cudaGetSymbolAddress((void**)&pa,   g_a);
    cudaGetSymbolAddress((void**)&psb0, g_sb0);
    cudaGetSymbolAddress((void**)&psb1, g_sb1);

    cudaFuncSetAttribute(tgemm_kernel,
                         cudaFuncAttributeMaxDynamicSharedMemorySize, SMEM_BYTES);

    scores_kernel<<<NB, 256>>>(hs, rw, rb);
    topk_kernel<<<1, 256>>>();
    gather_rms_kernel<<<KSEL, 512>>>(hs, ln1, px, ph, 1);

    const int rdD = (KSEL * DD / 4 + 255) / 256;   // 256 blocks
    const int rdI = (KSEL * II / 4 + 255) / 256;   // 688 blocks

    // v = h @ wv + bv             (K=2048, N=2048, 16 splits of 128)
    tgemm_kernel<<<dim3(DD/128, 16, 1), 256, SMEM_BYTES>>>(
        ph, wv, wv, psb0, psb0, DD, DD, 128);
    red_bias_kernel<16><<<rdD, 256>>>(psb0, bv, pv, DD);
    // x2 = x + v @ wo             (16 splits)
    tgemm_kernel<<<dim3(DD/128, 16, 1), 256, SMEM_BYTES>>>(
        pv, wo, wo, psb0, psb0, DD, DD, 128);
    red_resid_kernel<16><<<rdD, 256>>>(psb0, px, px2, DD);
    // h2 = rms(x2)
    gather_rms_kernel<<<KSEL, 512>>>(px2, ln2, nullptr, ph2, 0);
    // g = h2 @ w_gate ; u = h2 @ w_up  (one launch, K=2048, N=5504, 4 splits)
    tgemm_kernel<<<dim3(II/128, 4, 2), 256, SMEM_BYTES>>>(
        ph2, wg, wu, psb0, psb1, II, DD, 512);
    red_silu_kernel<4><<<rdI, 256>>>(psb0, psb1, pa, II);
    // out[sel] = x2 + a @ w_down  (K=5504, N=2048, 16 splits of 352)
    tgemm_kernel<<<dim3(DD/128, 16, 1), 256, SMEM_BYTES>>>(
        pa, wd, wd, psb0, psb0, DD, II, 352);
    copy_kernel<<<256, 256>>>((const float4*)hs, (float4*)out, (NB * DD) / 4);
    red_scatter_kernel<16><<<rdD, 256>>>(psb0, px2, out);
}

// round 8
// speedup vs baseline: 1.3464x; 1.3464x over previous
#include <cuda_runtime.h>
#include <cuda_fp16.h>
#include <math.h>

#define NB   256
#define DD   2048
#define II   5504
#define KSEL 128

// ---------------- scratch (device globals) ----------------------------------
__device__ float  g_scores[NB];
__device__ int    g_sel[KSEL];
__device__ float  g_x [KSEL*DD];     // gathered selected rows (residual)
__device__ float  g_x2[KSEL*DD];     // post-attention residual
__device__ __half g_h [KSEL*DD];     // rms(x)      fp16 (GEMM A)
__device__ __half g_v [KSEL*DD];     // h@wv+bv     fp16 (GEMM A)
__device__ __half g_h2[KSEL*DD];     // rms(x2)     fp16 (GEMM A)
__device__ __half g_a [KSEL*II];     // silu(g)*u   fp16 (GEMM A)
#define SBELEMS (16*KSEL*DD)         // 16 splits x 128 x 2048 (>= 4*128*5504)
__device__ float  g_sb0[SBELEMS];
__device__ float  g_sb1[SBELEMS];

// ---------------- router scores ---------------------------------------------
__global__ __launch_bounds__(256) void scores_kernel(
    const float* __restrict__ hs, const float* __restrict__ rw,
    const float* __restrict__ rb)
{
    int b = blockIdx.x;
    const float4* row = (const float4*)(hs + (size_t)b * DD);
    const float4* w4  = (const float4*)rw;
    float s = 0.f;
    #pragma unroll
    for (int j = 0; j < 2; j++) {
        int i = j * 256 + threadIdx.x;
        float4 v = row[i], w = w4[i];
        s += v.x * w.x + v.y * w.y + v.z * w.z + v.w * w.w;
    }
    __shared__ float sm[256];
    sm[threadIdx.x] = s; __syncthreads();
    for (int st = 128; st > 0; st >>= 1) {
        if (threadIdx.x < st) sm[threadIdx.x] += sm[threadIdx.x + st];
        __syncthreads();
    }
    if (threadIdx.x == 0) g_scores[b] = sm[0] + rb[0];
}

// ---------------- top-k selection -------------------------------------------
__global__ __launch_bounds__(256) void topk_kernel()
{
    __shared__ float s[NB];
    __shared__ int   flag[NB];
    int t = threadIdx.x;
    s[t] = g_scores[t];
    __syncthreads();
    float mine = s[t];
    int rank = 0;
    for (int j = 0; j < NB; j++) {
        float o = s[j];
        if (o > mine || (o == mine && j < t)) rank++;
    }
    flag[t] = (rank < KSEL) ? 1 : 0;
    __syncthreads();
    if (t == 0) {
        int c = 0;
        for (int j = 0; j < NB; j++) if (flag[j]) g_sel[c++] = j;
    }
}

// ---------------- passthrough copy ------------------------------------------
__global__ __launch_bounds__(256) void copy_kernel(
    const float4* __restrict__ src, float4* __restrict__ dst, int n4)
{
    for (int i = blockIdx.x * blockDim.x + threadIdx.x; i < n4;
         i += gridDim.x * blockDim.x)
        dst[i] = src[i];
}

// ---------------- gather + RMSNorm -> fp16 ----------------------------------
__global__ __launch_bounds__(512) void gather_rms_kernel(
    const float* __restrict__ src_full, const float* __restrict__ w,
    float* __restrict__ x_out, __half* __restrict__ h_out, int gather)
{
    int r = blockIdx.x;
    int t = threadIdx.x;
    const float* src = gather ? (src_full + (size_t)g_sel[r] * DD)
                              : (src_full + (size_t)r * DD);
    float4 v = ((const float4*)src)[t];
    float ss = v.x * v.x + v.y * v.y + v.z * v.z + v.w * v.w;
    __shared__ float sm[512];
    sm[t] = ss; __syncthreads();
    for (int st = 256; st > 0; st >>= 1) {
        if (t < st) sm[t] += sm[t + st];
        __syncthreads();
    }
    float inv = rsqrtf(sm[0] * (1.0f / (float)DD) + 1e-6f);
    if (x_out) ((float4*)(x_out + (size_t)r * DD))[t] = v;
    float4 wv = ((const float4*)w)[t];
    __half2* o = (__half2*)(h_out + (size_t)r * DD);
    o[2*t]     = __floats2half2_rn(v.x * inv * wv.x, v.y * inv * wv.y);
    o[2*t + 1] = __floats2half2_rn(v.z * inv * wv.z, v.w * inv * wv.w);
}

// ---------------- mma helpers ------------------------------------------------
__device__ __forceinline__ unsigned smaddr(const void* p) {
    return (unsigned)__cvta_generic_to_shared(p);
}
__device__ __forceinline__ void ldsm4(unsigned a, unsigned& r0, unsigned& r1,
                                      unsigned& r2, unsigned& r3) {
    asm volatile("ldmatrix.sync.aligned.m8n8.x4.shared.b16 {%0,%1,%2,%3}, [%4];"
                 : "=r"(r0), "=r"(r1), "=r"(r2), "=r"(r3) : "r"(a));
}
__device__ __forceinline__ void ldsm4t(unsigned a, unsigned& r0, unsigned& r1,
                                       unsigned& r2, unsigned& r3) {
    asm volatile("ldmatrix.sync.aligned.m8n8.x4.trans.shared.b16 {%0,%1,%2,%3}, [%4];"
                 : "=r"(r0), "=r"(r1), "=r"(r2), "=r"(r3) : "r"(a));
}
__device__ __forceinline__ void mma16816(float* c, const unsigned* a,
                                         const unsigned* b) {
    asm volatile("mma.sync.aligned.m16n8k16.row.col.f32.f16.f16.f32 "
                 "{%0,%1,%2,%3}, {%4,%5,%6,%7}, {%8,%9}, {%0,%1,%2,%3};"
                 : "+f"(c[0]), "+f"(c[1]), "+f"(c[2]), "+f"(c[3])
                 : "r"(a[0]), "r"(a[1]), "r"(a[2]), "r"(a[3]),
                   "r"(b[0]), "r"(b[1]));
}
#define CP_ASYNC16(dst, src) \
    asm volatile("cp.async.cg.shared.global [%0], [%1], 16;" \
                 :: "r"(dst), "l"(src))
#define CP_COMMIT()  asm volatile("cp.async.commit_group;")
#define CP_WAIT2()   asm volatile("cp.async.wait_group 2;")
#define CP_WAIT0()   asm volatile("cp.async.wait_group 0;")

// ---------------- HGEMM: Csplit[z] = A[128,Kslice] @ W[Kslice,N] -------------
// A fp16 [128,K] row-major (cp.async direct, XOR-swizzled smem).
// W fp32 [K,N] row-major (cp.async to smem, smem->smem fp16 convert).
// grid = (N/128, splits, nW). 256 threads, 2 CTAs/SM. BK=32.
// K and kPerSplit multiples of 32 (last split may be shorter, still mult of 32).
#define BK       32
#define A_STAGE_B   8192                // 128 rows x 64B, swizzled, no pad
#define B32_PITCH   128                 // floats per row (no pad)
#define B32_STAGE_F (BK*B32_PITCH)      // 4096 floats
#define BH_PITCH    136                 // halves per row (128 + 8 pad)
#define BH_STAGE_H  (BK*BH_PITCH)       // 4352 halves
#define NSTAGE   4
#define SMEM_BYTES (NSTAGE*A_STAGE_B + NSTAGE*B32_STAGE_F*4 + 2*BH_STAGE_H*2)

// A smem addressing: 128B line = 2 rows of 64B; 16B chunk c16 in row r at:
//   (r>>1)*128 + (r&1)*64 + ((c16 ^ ((r>>1)&3))<<4)
__device__ __forceinline__ unsigned a_off(int r, int c16) {
    return ((r >> 1) << 7) + ((r & 1) << 6) + ((c16 ^ ((r >> 1) & 3)) << 4);
}

__global__ __launch_bounds__(256, 2) void hgemm_kernel(
    const __half* __restrict__ A,
    const float* __restrict__ W0, const float* __restrict__ W1,
    float* __restrict__ C0, float* __restrict__ C1,
    int N, int K, int kPerSplit)
{
    extern __shared__ char smraw[];
    char*   As  = smraw;                                  // NSTAGE * 8192 B
    float*  B32 = (float*)(smraw + NSTAGE * A_STAGE_B);   // NSTAGE * 4096 f
    __half* Bh  = (__half*)(B32 + NSTAGE * B32_STAGE_F);  // 2 * 4352 h
    unsigned As_u  = smaddr(As);
    unsigned B32_u = smaddr(B32);

    const float* W = blockIdx.z ? W1 : W0;
    float* C       = blockIdx.z ? C1 : C0;

    const int tid  = threadIdx.x;
    const int lane = tid & 31, warp = tid >> 5;
    const int wm = warp & 3, wn = warp >> 2;     // 4 M-warps x 2 N-warps
    const int n0 = blockIdx.x * 128;
    const int kb = blockIdx.y * kPerSplit;
    const int ke = min(kb + kPerSplit, K);
    const int nch = (ke - kb) >> 5;              // 32-k chunks

    float acc[2][8][4];
    #pragma unroll
    for (int i = 0; i < 2; i++)
        #pragma unroll
        for (int j = 0; j < 8; j++)
            #pragma unroll
            for (int q = 0; q < 4; q++) acc[i][j][q] = 0.f;

    auto issue_copy = [&](int c) {
        int s = c & (NSTAGE - 1);
        int k0 = kb + c * BK;
        // A: 128x32 halves = 512 x 16B chunks, swizzled
        unsigned a_s = As_u + s * A_STAGE_B;
        #pragma unroll
        for (int j = 0; j < 2; j++) {
            int cc = tid + 256 * j;
            int row = cc >> 2, c16 = cc & 3;
            CP_ASYNC16(a_s + a_off(row, c16),
                       A + (size_t)row * K + k0 + c16 * 8);
        }
        // B: 32x128 floats = 1024 x 16B chunks, linear pitch 128
        unsigned b_s = B32_u + (s * B32_STAGE_F) * 4;
        #pragma unroll
        for (int j = 0; j < 4; j++) {
            int cc = tid + 256 * j;
            int row = cc >> 5, cs = cc & 31;
            CP_ASYNC16(b_s + (row * B32_PITCH + cs * 4) * 4,
                       W + (size_t)(k0 + row) * N + n0 + cs * 4);
        }
    };

    // convert B32 stage s -> Bh buffer d (fp32 -> fp16), float2 granularity
    auto convertB = [&](int s, int d) {
        const float2* src = (const float2*)(B32 + s * B32_STAGE_F);
        __half* dst = Bh + d * BH_STAGE_H;
        #pragma unroll
        for (int j = 0; j < 8; j++) {
            int f = tid + 256 * j;              // 2048 float2 per chunk
            int row = f >> 6, c2 = f & 63;      // B32_PITCH/2 = 64 float2/row
            float2 v = src[row * (B32_PITCH / 2) + c2];
            *(__half2*)(dst + row * BH_PITCH + c2 * 2) =
                __floats2half2_rn(v.x, v.y);
        }
    };

    auto mmastage = [&](int s, int d) {
        unsigned a_s = As_u + s * A_STAGE_B;
        const __half* Bb = Bh + d * BH_STAGE_H;
        #pragma unroll
        for (int kk = 0; kk < 2; kk++) {
            unsigned af[2][4];
            #pragma unroll
            for (int at = 0; at < 2; at++) {
                int r = wm * 32 + at * 16 + (lane & 7) + ((lane >> 3) & 1) * 8;
                int c16 = kk * 2 + (lane >> 4);
                ldsm4(a_s + a_off(r, c16),
                      af[at][0], af[at][1], af[at][2], af[at][3]);
            }
            unsigned bf[8][2];
            #pragma unroll
            for (int nq = 0; nq < 4; nq++) {
                int r = kk * 16 + ((lane >> 3) & 1) * 8 + (lane & 7);
                int c = wn * 64 + nq * 16 + (lane >> 4) * 8;
                unsigned r0, r1, r2, r3;
                ldsm4t(smaddr(Bb + r * BH_PITCH + c), r0, r1, r2, r3);
                bf[nq*2][0] = r0;   bf[nq*2][1] = r1;
                bf[nq*2+1][0] = r2; bf[nq*2+1][1] = r3;
            }
            #pragma unroll
            for (int at = 0; at < 2; at++)
                #pragma unroll
                for (int nb = 0; nb < 8; nb++)
                    mma16816(acc[at][nb], af[at], bf[nb]);
        }
    };

    // prologue: 3 chunks in flight
    #pragma unroll
    for (int c = 0; c < NSTAGE - 1; c++) {
        if (c < nch) issue_copy(c);
        CP_COMMIT();
    }

    for (int c = 0; c < nch; c++) {
        CP_WAIT2();
        __syncthreads();                 // chunk c resident; slot c-1 free
        if (c + NSTAGE - 1 < nch) issue_copy(c + NSTAGE - 1);
        CP_COMMIT();
        convertB(c & (NSTAGE - 1), c & 1);
        __syncthreads();                 // Bh(c) visible to all warps
        mmastage(c & (NSTAGE - 1), c & 1);
    }
    CP_WAIT0();

    float* Cs = C + (size_t)blockIdx.y * 128 * N;
    int g = lane >> 2, q = lane & 3;
    #pragma unroll
    for (int at = 0; at < 2; at++) {
        int r = wm * 32 + at * 16 + g;
        #pragma unroll
        for (int nb = 0; nb < 8; nb++) {
            int cix = n0 + wn * 64 + nb * 8 + 2 * q;
            *(float2*)&Cs[(size_t)r * N + cix] =
                make_float2(acc[at][nb][0], acc[at][nb][1]);
            *(float2*)&Cs[(size_t)(r + 8) * N + cix] =
                make_float2(acc[at][nb][2], acc[at][nb][3]);
        }
    }
}

// ---------------- split-K reductions with fused epilogues --------------------
template<int SPLITS>
__global__ __launch_bounds__(256) void red_bias_h_kernel(
    const float* __restrict__ S, const float* __restrict__ bias,
    __half* __restrict__ out, int N)
{
    int i = blockIdx.x * 256 + threadIdx.x;
    int tot = KSEL * N / 4;
    if (i >= tot) return;
    const float4* S4 = (const float4*)S;
    size_t stride = (size_t)KSEL * N / 4;
    float4 s = S4[i];
    #pragma unroll
    for (int z = 1; z < SPLITS; z++) {
        float4 t = S4[z * stride + i];
        s.x += t.x; s.y += t.y; s.z += t.z; s.w += t.w;
    }
    float4 b = ((const float4*)bias)[i % (N / 4)];
    s.x += b.x; s.y += b.y; s.z += b.z; s.w += b.w;
    __half2* o = (__half2*)out;
    o[2*i]     = __floats2half2_rn(s.x, s.y);
    o[2*i + 1] = __floats2half2_rn(s.z, s.w);
}

template<int SPLITS>
__global__ __launch_bounds__(256) void red_resid_kernel(
    const float* __restrict__ S, const float* __restrict__ X,
    float* __restrict__ out, int N)
{
    int i = blockIdx.x * 256 + threadIdx.x;
    int tot = KSEL * N / 4;
    if (i >= tot) return;
    const float4* S4 = (const float4*)S;
    size_t stride = (size_t)KSEL * N / 4;
    float4 s = S4[i];
    #pragma unroll
    for (int z = 1; z < SPLITS; z++) {
        float4 t = S4[z * stride + i];
        s.x += t.x; s.y += t.y; s.z += t.z; s.w += t.w;
    }
    float4 x = ((const float4*)X)[i];
    s.x += x.x; s.y += x.y; s.z += x.z; s.w += x.w;
    ((float4*)out)[i] = s;
}

template<int SPLITS>
__global__ __launch_bounds__(256) void red_silu_kernel(
    const float* __restrict__ Sg, const float* __restrict__ Su,
    __half* __restrict__ out, int N)
{
    int i = blockIdx.x * 256 + threadIdx.x;
    int tot = KSEL * N / 4;
    if (i >= tot) return;
    const float4* G4 = (const float4*)Sg;
    const float4* U4 = (const float4*)Su;
    size_t stride = (size_t)KSEL * N / 4;
    float4 g = G4[i], u = U4[i];
    #pragma unroll
    for (int z = 1; z < SPLITS; z++) {
        float4 t = G4[z * stride + i];
        g.x += t.x; g.y += t.y; g.z += t.z; g.w += t.w;
        float4 v = U4[z * stride + i];
        u.x += v.x; u.y += v.y; u.z += v.z; u.w += v.w;
    }
    float a0 = g.x / (1.f + expf(-g.x)) * u.x;
    float a1 = g.y / (1.f + expf(-g.y)) * u.y;
    float a2 = g.z / (1.f + expf(-g.z)) * u.z;
    float a3 = g.w / (1.f + expf(-g.w)) * u.w;
    __half2* o = (__half2*)out;
    o[2*i]     = __floats2half2_rn(a0, a1);
    o[2*i + 1] = __floats2half2_rn(a2, a3);
}

template<int SPLITS>
__global__ __launch_bounds__(256) void red_scatter_kernel(
    const float* __restrict__ S, const float* __restrict__ X2,
    float* __restrict__ out)   // out: [256][2048]
{
    int i = blockIdx.x * 256 + threadIdx.x;
    int tot = KSEL * DD / 4;
    if (i >= tot) return;
    const float4* S4 = (const float4*)S;
    size_t stride = (size_t)KSEL * DD / 4;
    float4 s = S4[i];
    #pragma unroll
    for (int z = 1; z < SPLITS; z++) {
        float4 t = S4[z * stride + i];
        s.x += t.x; s.y += t.y; s.z += t.z; s.w += t.w;
    }
    float4 x = ((const float4*)X2)[i];
    s.x += x.x; s.y += x.y; s.z += x.z; s.w += x.w;
    int row = i / (DD / 4), c4 = i % (DD / 4);
    ((float4*)out)[(size_t)g_sel[row] * (DD / 4) + c4] = s;
}

// ---------------- launch -----------------------------------------------------
extern "C" void kernel_launch(void* const* d_in, const int* in_sizes, int n_in,
                              void* d_out, int out_size)
{
    const float* hs  = (const float*)d_in[0];
    const float* rw  = (const float*)d_in[3];
    const float* rb  = (const float*)d_in[4];
    const float* ln1 = (const float*)d_in[5];
    const float* ln2 = (const float*)d_in[6];
    // wq/bq/wk/bk (d_in[7..10]) dead: softmax over a single key == 1 -> o == v
    const float* wv  = (const float*)d_in[11];
    const float* bv  = (const float*)d_in[12];
    const float* wo  = (const float*)d_in[13];
    const float* wg  = (const float*)d_in[14];
    const float* wu  = (const float*)d_in[15];
    const float* wd  = (const float*)d_in[16];
    float* out = (float*)d_out;

    float *px, *px2, *psb0, *psb1;
    __half *ph, *pv, *ph2, *pa;
    cudaGetSymbolAddress((void**)&px,   g_x);
    cudaGetSymbolAddress((void**)&px2,  g_x2);
    cudaGetSymbolAddress((void**)&ph,   g_h);
    cudaGetSymbolAddress((void**)&pv,   g_v);
    cudaGetSymbolAddress((void**)&ph2,  g_h2);
    cudaGetSymbolAddress((void**)&pa,   g_a);
    cudaGetSymbolAddress((void**)&psb0, g_sb0);
    cudaGetSymbolAddress((void**)&psb1, g_sb1);

    cudaFuncSetAttribute(hgemm_kernel,
                         cudaFuncAttributeMaxDynamicSharedMemorySize, SMEM_BYTES);

    scores_kernel<<<NB, 256>>>(hs, rw, rb);
    topk_kernel<<<1, 256>>>();
    gather_rms_kernel<<<KSEL, 512>>>(hs, ln1, px, ph, 1);

    const int rdD = (KSEL * DD / 4 + 255) / 256;   // 256 blocks
    const int rdI = (KSEL * II / 4 + 255) / 256;   // 688 blocks

    // v = h @ wv + bv            (K=2048, N=2048, 16 splits of 128)
    hgemm_kernel<<<dim3(DD/128, 16, 1), 256, SMEM_BYTES>>>(
        ph, wv, wv, psb0, psb0, DD, DD, 128);
    red_bias_h_kernel<16><<<rdD, 256>>>(psb0, bv, pv, DD);
    // x2 = x + v @ wo            (16 splits)
    hgemm_kernel<<<dim3(DD/128, 16, 1), 256, SMEM_BYTES>>>(
        pv, wo, wo, psb0, psb0, DD, DD, 128);
    red_resid_kernel<16><<<rdD, 256>>>(psb0, px, px2, DD);
    // h2 = rms(x2)
    gather_rms_kernel<<<KSEL, 512>>>(px2, ln2, nullptr, ph2, 0);
    // g = h2 @ w_gate ; u = h2 @ w_up  (one launch, K=2048, N=5504, 4 splits)
    hgemm_kernel<<<dim3(II/128, 4, 2), 256, SMEM_BYTES>>>(
        ph2, wg, wu, psb0, psb1, II, DD, 512);
    red_silu_kernel<4><<<rdI, 256>>>(psb0, psb1, pa, II);
    // out[sel] = x2 + a @ w_down (K=5504, N=2048, 16 splits of 352)
    hgemm_kernel<<<dim3(DD/128, 16, 1), 256, SMEM_BYTES>>>(
        pa, wd, wd, psb0, psb0, DD, II, 352);
    copy_kernel<<<256, 256>>>((const float4*)hs, (float4*)out, (NB * DD) / 4);
    red_scatter_kernel<16><<<rdD, 256>>>(psb0, px2, out);
}

// round 10
// speedup vs baseline: 1.5475x; 1.1494x over previous
#include <cuda_runtime.h>
#include <cuda_fp16.h>
#include <math.h>

#define NB   256
#define DD   2048
#define II   5504
#define KSEL 128

// ---------------- scratch (device globals) ----------------------------------
__device__ float  g_scores[NB];
__device__ int    g_sel[KSEL];
__device__ float  g_x [KSEL*DD];     // gathered selected rows (residual)
__device__ float  g_x2[KSEL*DD];     // post-attention residual
__device__ __half g_h [KSEL*DD];     // rms(x)      fp16 (GEMM A)
__device__ __half g_v [KSEL*DD];     // h@wv+bv     fp16 (GEMM A)
__device__ __half g_h2[KSEL*DD];     // rms(x2)     fp16 (GEMM A)
__device__ __half g_a [KSEL*II];     // silu(g)*u   fp16 (GEMM A)
#define SBELEMS (16*KSEL*DD)         // 16 splits x 128 x 2048 (>= 3*128*5504)
__device__ float  g_sb0[SBELEMS];
__device__ float  g_sb1[SBELEMS];

// ---------------- router scores ---------------------------------------------
__global__ __launch_bounds__(256) void scores_kernel(
    const float* __restrict__ hs, const float* __restrict__ rw,
    const float* __restrict__ rb)
{
    int b = blockIdx.x;
    const float4* row = (const float4*)(hs + (size_t)b * DD);
    const float4* w4  = (const float4*)rw;
    float s = 0.f;
    #pragma unroll
    for (int j = 0; j < 2; j++) {
        int i = j * 256 + threadIdx.x;
        float4 v = row[i], w = w4[i];
        s += v.x * w.x + v.y * w.y + v.z * w.z + v.w * w.w;
    }
    __shared__ float sm[256];
    sm[threadIdx.x] = s; __syncthreads();
    for (int st = 128; st > 0; st >>= 1) {
        if (threadIdx.x < st) sm[threadIdx.x] += sm[threadIdx.x + st];
        __syncthreads();
    }
    if (threadIdx.x == 0) g_scores[b] = sm[0] + rb[0];
}

// ---------------- top-k selection -------------------------------------------
__global__ __launch_bounds__(256) void topk_kernel()
{
    __shared__ float s[NB];
    __shared__ int   flag[NB];
    int t = threadIdx.x;
    s[t] = g_scores[t];
    __syncthreads();
    float mine = s[t];
    int rank = 0;
    for (int j = 0; j < NB; j++) {
        float o = s[j];
        if (o > mine || (o == mine && j < t)) rank++;
    }
    flag[t] = (rank < KSEL) ? 1 : 0;
    __syncthreads();
    if (t == 0) {
        int c = 0;
        for (int j = 0; j < NB; j++) if (flag[j]) g_sel[c++] = j;
    }
}

// ---------------- passthrough copy ------------------------------------------
__global__ __launch_bounds__(256) void copy_kernel(
    const float4* __restrict__ src, float4* __restrict__ dst, int n4)
{
    for (int i = blockIdx.x * blockDim.x + threadIdx.x; i < n4;
         i += gridDim.x * blockDim.x)
        dst[i] = src[i];
}

// ---------------- gather + RMSNorm -> fp16 ----------------------------------
__global__ __launch_bounds__(512) void gather_rms_kernel(
    const float* __restrict__ src_full, const float* __restrict__ w,
    float* __restrict__ x_out, __half* __restrict__ h_out, int gather)
{
    int r = blockIdx.x;
    int t = threadIdx.x;
    const float* src = gather ? (src_full + (size_t)g_sel[r] * DD)
                              : (src_full + (size_t)r * DD);
    float4 v = ((const float4*)src)[t];
    float ss = v.x * v.x + v.y * v.y + v.z * v.z + v.w * v.w;
    __shared__ float sm[512];
    sm[t] = ss; __syncthreads();
    for (int st = 256; st > 0; st >>= 1) {
        if (t < st) sm[t] += sm[t + st];
        __syncthreads();
    }
    float inv = rsqrtf(sm[0] * (1.0f / (float)DD) + 1e-6f);
    if (x_out) ((float4*)(x_out + (size_t)r * DD))[t] = v;
    float4 wv = ((const float4*)w)[t];
    __half2* o = (__half2*)(h_out + (size_t)r * DD);
    o[2*t]     = __floats2half2_rn(v.x * inv * wv.x, v.y * inv * wv.y);
    o[2*t + 1] = __floats2half2_rn(v.z * inv * wv.z, v.w * inv * wv.w);
}

// ---------------- mma helpers ------------------------------------------------
__device__ __forceinline__ unsigned smaddr(const void* p) {
    return (unsigned)__cvta_generic_to_shared(p);
}
__device__ __forceinline__ void ldsm4(unsigned a, unsigned& r0, unsigned& r1,
                                      unsigned& r2, unsigned& r3) {
    asm volatile("ldmatrix.sync.aligned.m8n8.x4.shared.b16 {%0,%1,%2,%3}, [%4];"
                 : "=r"(r0), "=r"(r1), "=r"(r2), "=r"(r3) : "r"(a));
}
__device__ __forceinline__ void ldsm4t(unsigned a, unsigned& r0, unsigned& r1,
                                       unsigned& r2, unsigned& r3) {
    asm volatile("ldmatrix.sync.aligned.m8n8.x4.trans.shared.b16 {%0,%1,%2,%3}, [%4];"
                 : "=r"(r0), "=r"(r1), "=r"(r2), "=r"(r3) : "r"(a));
}
__device__ __forceinline__ void mma16816(float* c, const unsigned* a,
                                         const unsigned* b) {
    asm volatile("mma.sync.aligned.m16n8k16.row.col.f32.f16.f16.f32 "
                 "{%0,%1,%2,%3}, {%4,%5,%6,%7}, {%8,%9}, {%0,%1,%2,%3};"
                 : "+f"(c[0]), "+f"(c[1]), "+f"(c[2]), "+f"(c[3])
                 : "r"(a[0]), "r"(a[1]), "r"(a[2]), "r"(a[3]),
                   "r"(b[0]), "r"(b[1]));
}
#define CP_ASYNC16(dst, src) \
    asm volatile("cp.async.cg.shared.global [%0], [%1], 16;" \
                 :: "r"(dst), "l"(src))
#define CP_COMMIT()  asm volatile("cp.async.commit_group;")
#define CP_WAIT1()   asm volatile("cp.async.wait_group 1;")
#define CP_WAIT0()   asm volatile("cp.async.wait_group 0;")

// ---------------- HGEMM: Csplit[z] = A[128,Kslice] @ W[Kslice,N] -------------
// A fp16 [128,K] row-major (cp.async direct, XOR-swizzled smem).
// W fp32 [K,N] row-major (cp.async to smem, smem->smem fp16 convert).
// grid = (N/128, splits, nW). 256 threads, 2 CTAs/SM. BK=32, 3 stages.
// K and kPerSplit multiples of 32.
#define BK       32
#define A_STAGE_B   8192                // 128 rows x 64B, swizzled
#define B32_PITCH   128                 // floats per row
#define B32_STAGE_F (BK*B32_PITCH)      // 4096 floats = 16KB
#define BH_PITCH    136                 // halves per row (128 + 8 pad)
#define BH_STAGE_H  (BK*BH_PITCH)       // 4352 halves
#define NSTAGE   3
#define SMEM_BYTES (NSTAGE*A_STAGE_B + NSTAGE*B32_STAGE_F*4 + 2*BH_STAGE_H*2)
// = 24576 + 49152 + 17408 = 91136 B -> 2 CTAs/SM

// A smem: 128B line = 2 rows of 64B; 16B chunk c16 of row r at:
__device__ __forceinline__ unsigned a_off(int r, int c16) {
    return ((r >> 1) << 7) + ((r & 1) << 6) + ((c16 ^ ((r >> 1) & 3)) << 4);
}

__global__ __launch_bounds__(256, 2) void hgemm_kernel(
    const __half* __restrict__ A,
    const float* __restrict__ W0, const float* __restrict__ W1,
    float* __restrict__ C0, float* __restrict__ C1,
    int N, int K, int kPerSplit)
{
    extern __shared__ char smraw[];
    char*   As  = smraw;                                  // NSTAGE * 8192 B
    float*  B32 = (float*)(smraw + NSTAGE * A_STAGE_B);   // NSTAGE * 4096 f
    __half* Bh  = (__half*)(B32 + NSTAGE * B32_STAGE_F);  // 2 * 4352 h
    unsigned As_u  = smaddr(As);
    unsigned B32_u = smaddr(B32);

    const float* W = blockIdx.z ? W1 : W0;
    float* C       = blockIdx.z ? C1 : C0;

    const int tid  = threadIdx.x;
    const int lane = tid & 31, warp = tid >> 5;
    const int wm = warp & 3, wn = warp >> 2;     // 4 M-warps x 2 N-warps
    const int n0 = blockIdx.x * 128;
    const int kb = blockIdx.y * kPerSplit;
    const int ke = min(kb + kPerSplit, K);
    const int nch = (ke - kb) >> 5;              // 32-k chunks

    float acc[2][8][4];
    #pragma unroll
    for (int i = 0; i < 2; i++)
        #pragma unroll
        for (int j = 0; j < 8; j++)
            #pragma unroll
            for (int q = 0; q < 4; q++) acc[i][j][q] = 0.f;

    auto issue_copy = [&](int c) {
        int s = c % NSTAGE;
        int k0 = kb + c * BK;
        // A: 128x32 halves = 512 x 16B chunks, swizzled
        unsigned a_s = As_u + s * A_STAGE_B;
        #pragma unroll
        for (int j = 0; j < 2; j++) {
            int cc = tid + 256 * j;
            int row = cc >> 2, c16 = cc & 3;
            CP_ASYNC16(a_s + a_off(row, c16),
                       A + (size_t)row * K + k0 + c16 * 8);
        }
        // B: 32x128 floats = 1024 x 16B chunks, linear pitch 128
        unsigned b_s = B32_u + (s * B32_STAGE_F) * 4;
        #pragma unroll
        for (int j = 0; j < 4; j++) {
            int cc = tid + 256 * j;
            int row = cc >> 5, cs = cc & 31;
            CP_ASYNC16(b_s + (row * B32_PITCH + cs * 4) * 4,
                       W + (size_t)(k0 + row) * N + n0 + cs * 4);
        }
    };

    // convert B32 stage s -> Bh buffer d (fp32 -> fp16)
    auto convertB = [&](int s, int d) {
        const float2* src = (const float2*)(B32 + s * B32_STAGE_F);
        __half* dst = Bh + d * BH_STAGE_H;
        #pragma unroll
        for (int j = 0; j < 8; j++) {
            int f = tid + 256 * j;              // 2048 float2 per chunk
            int row = f >> 6, c2 = f & 63;
            float2 v = src[row * (B32_PITCH / 2) + c2];
            *(__half2*)(dst + row * BH_PITCH + c2 * 2) =
                __floats2half2_rn(v.x, v.y);
        }
    };

    auto mmastage = [&](int s, int d) {
        unsigned a_s = As_u + s * A_STAGE_B;
        const __half* Bb = Bh + d * BH_STAGE_H;
        #pragma unroll
        for (int kk = 0; kk < 2; kk++) {
            unsigned af[2][4];
            #pragma unroll
            for (int at = 0; at < 2; at++) {
                int r = wm * 32 + at * 16 + (lane & 7) + ((lane >> 3) & 1) * 8;
                int c16 = kk * 2 + (lane >> 4);
                ldsm4(a_s + a_off(r, c16),
                      af[at][0], af[at][1], af[at][2], af[at][3]);
            }
            unsigned bf[8][2];
            #pragma unroll
            for (int nq = 0; nq < 4; nq++) {
                int r = kk * 16 + ((lane >> 3) & 1) * 8 + (lane & 7);
                int c = wn * 64 + nq * 16 + (lane >> 4) * 8;
                unsigned r0, r1, r2, r3;
                ldsm4t(smaddr(Bb + r * BH_PITCH + c), r0, r1, r2, r3);
                bf[nq*2][0] = r0;   bf[nq*2][1] = r1;
                bf[nq*2+1][0] = r2; bf[nq*2+1][1] = r3;
            }
            #pragma unroll
            for (int at = 0; at < 2; at++)
                #pragma unroll
                for (int nb = 0; nb < 8; nb++)
                    mma16816(acc[at][nb], af[at], bf[nb]);
        }
    };

    // prologue: 2 chunks in flight
    #pragma unroll
    for (int c = 0; c < NSTAGE - 1; c++) {
        if (c < nch) issue_copy(c);
        CP_COMMIT();
    }

    for (int c = 0; c < nch; c++) {
        CP_WAIT1();                      // chunk c resident (own copies)
        __syncthreads();                 // all threads' chunk c visible;
                                         // mma(c-1) readers done
        if (c + NSTAGE - 1 < nch) issue_copy(c + NSTAGE - 1);
        CP_COMMIT();
        convertB(c % NSTAGE, c & 1);
        __syncthreads();                 // Bh(c) visible to all warps
        mmastage(c % NSTAGE, c & 1);
    }
    CP_WAIT0();

    float* Cs = C + (size_t)blockIdx.y * 128 * N;
    int g = lane >> 2, q = lane & 3;
    #pragma unroll
    for (int at = 0; at < 2; at++) {
        int r = wm * 32 + at * 16 + g;
        #pragma unroll
        for (int nb = 0; nb < 8; nb++) {
            int cix = n0 + wn * 64 + nb * 8 + 2 * q;
            *(float2*)&Cs[(size_t)r * N + cix] =
                make_float2(acc[at][nb][0], acc[at][nb][1]);
            *(float2*)&Cs[(size_t)(r + 8) * N + cix] =
                make_float2(acc[at][nb][2], acc[at][nb][3]);
        }
    }
}

// ---------------- split-K reductions with fused epilogues --------------------
template<int SPLITS>
__global__ __launch_bounds__(256) void red_bias_h_kernel(
    const float* __restrict__ S, const float* __restrict__ bias,
    __half* __restrict__ out, int N)
{
    int i = blockIdx.x * 256 + threadIdx.x;
    int tot = KSEL * N / 4;
    if (i >= tot) return;
    const float4* S4 = (const float4*)S;
    size_t stride = (size_t)KSEL * N / 4;
    float4 s = S4[i];
    #pragma unroll
    for (int z = 1; z < SPLITS; z++) {
        float4 t = S4[z * stride + i];
        s.x += t.x; s.y += t.y; s.z += t.z; s.w += t.w;
    }
    float4 b = ((const float4*)bias)[i % (N / 4)];
    s.x += b.x; s.y += b.y; s.z += b.z; s.w += b.w;
    __half2* o = (__half2*)out;
    o[2*i]     = __floats2half2_rn(s.x, s.y);
    o[2*i + 1] = __floats2half2_rn(s.z, s.w);
}

template<int SPLITS>
__global__ __launch_bounds__(256) void red_resid_kernel(
    const float* __restrict__ S, const float* __restrict__ X,
    float* __restrict__ out, int N)
{
    int i = blockIdx.x * 256 + threadIdx.x;
    int tot = KSEL * N / 4;
    if (i >= tot) return;
    const float4* S4 = (const float4*)S;
    size_t stride = (size_t)KSEL * N / 4;
    float4 s = S4[i];
    #pragma unroll
    for (int z = 1; z < SPLITS; z++) {
        float4 t = S4[z * stride + i];
        s.x += t.x; s.y += t.y; s.z += t.z; s.w += t.w;
    }
    float4 x = ((const float4*)X)[i];
    s.x += x.x; s.y += x.y; s.z += x.z; s.w += x.w;
    ((float4*)out)[i] = s;
}

template<int SPLITS>
__global__ __launch_bounds__(256) void red_silu_kernel(
    const float* __restrict__ Sg, const float* __restrict__ Su,
    __half* __restrict__ out, int N)
{
    int i = blockIdx.x * 256 + threadIdx.x;
    int tot = KSEL * N / 4;
    if (i >= tot) return;
    const float4* G4 = (const float4*)Sg;
    const float4* U4 = (const float4*)Su;
    size_t stride = (size_t)KSEL * N / 4;
    float4 g = G4[i], u = U4[i];
    #pragma unroll
    for (int z = 1; z < SPLITS; z++) {
        float4 t = G4[z * stride + i];
        g.x += t.x; g.y += t.y; g.z += t.z; g.w += t.w;
        float4 v = U4[z * stride + i];
        u.x += v.x; u.y += v.y; u.z += v.z; u.w += v.w;
    }
    float a0 = g.x / (1.f + expf(-g.x)) * u.x;
    float a1 = g.y / (1.f + expf(-g.y)) * u.y;
    float a2 = g.z / (1.f + expf(-g.z)) * u.z;
    float a3 = g.w / (1.f + expf(-g.w)) * u.w;
    __half2* o = (__half2*)out;
    o[2*i]     = __floats2half2_rn(a0, a1);
    o[2*i + 1] = __floats2half2_rn(a2, a3);
}

template<int SPLITS>
__global__ __launch_bounds__(256) void red_scatter_kernel(
    const float* __restrict__ S, const float* __restrict__ X2,
    float* __restrict__ out)   // out: [256][2048]
{
    int i = blockIdx.x * 256 + threadIdx.x;
    int tot = KSEL * DD / 4;
    if (i >= tot) return;
    const float4* S4 = (const float4*)S;
    size_t stride = (size_t)KSEL * DD / 4;
    float4 s = S4[i];
    #pragma unroll
    for (int z = 1; z < SPLITS; z++) {
        float4 t = S4[z * stride + i];
        s.x += t.x; s.y += t.y; s.z += t.z; s.w += t.w;
    }
    float4 x = ((const float4*)X2)[i];
    s.x += x.x; s.y += x.y; s.z += x.z; s.w += x.w;
    int row = i / (DD / 4), c4 = i % (DD / 4);
    ((float4*)out)[(size_t)g_sel[row] * (DD / 4) + c4] = s;
}

// ---------------- launch -----------------------------------------------------
extern "C" void kernel_launch(void* const* d_in, const int* in_sizes, int n_in,
                              void* d_out, int out_size)
{
    const float* hs  = (const float*)d_in[0];
    const float* rw  = (const float*)d_in[3];
    const float* rb  = (const float*)d_in[4];
    const float* ln1 = (const float*)d_in[5];
    const float* ln2 = (const float*)d_in[6];
    // wq/bq/wk/bk (d_in[7..10]) dead: softmax over a single key == 1 -> o == v
    const float* wv  = (const float*)d_in[11];
    const float* bv  = (const float*)d_in[12];
    const float* wo  = (const float*)d_in[13];
    const float* wg  = (const float*)d_in[14];
    const float* wu  = (const float*)d_in[15];
    const float* wd  = (const float*)d_in[16];
    float* out = (float*)d_out;

    float *px, *px2, *psb0, *psb1;
    __half *ph, *pv, *ph2, *pa;
    cudaGetSymbolAddress((void**)&px,   g_x);
    cudaGetSymbolAddress((void**)&px2,  g_x2);
    cudaGetSymbolAddress((void**)&ph,   g_h);
    cudaGetSymbolAddress((void**)&pv,   g_v);
    cudaGetSymbolAddress((void**)&ph2,  g_h2);
    cudaGetSymbolAddress((void**)&pa,   g_a);
    cudaGetSymbolAddress((void**)&psb0, g_sb0);
    cudaGetSymbolAddress((void**)&psb1, g_sb1);

    cudaFuncSetAttribute(hgemm_kernel,
                         cudaFuncAttributeMaxDynamicSharedMemorySize, SMEM_BYTES);

    scores_kernel<<<NB, 256>>>(hs, rw, rb);
    topk_kernel<<<1, 256>>>();
    gather_rms_kernel<<<KSEL, 512>>>(hs, ln1, px, ph, 1);

    const int rdD = (KSEL * DD / 4 + 255) / 256;   // 256 blocks
    const int rdI = (KSEL * II / 4 + 255) / 256;   // 688 blocks

    // v = h @ wv + bv            (K=2048, N=2048, 16 splits of 128)
    hgemm_kernel<<<dim3(DD/128, 16, 1), 256, SMEM_BYTES>>>(
        ph, wv, wv, psb0, psb0, DD, DD, 128);
    red_bias_h_kernel<16><<<rdD, 256>>>(psb0, bv, pv, DD);
    // x2 = x + v @ wo            (16 splits)
    hgemm_kernel<<<dim3(DD/128, 16, 1), 256, SMEM_BYTES>>>(
        pv, wo, wo, psb0, psb0, DD, DD, 128);
    red_resid_kernel<16><<<rdD, 256>>>(psb0, px, px2, DD);
    // h2 = rms(x2)
    gather_rms_kernel<<<KSEL, 512>>>(px2, ln2, nullptr, ph2, 0);
    // g = h2 @ w_gate ; u = h2 @ w_up  (one launch, K=2048, N=5504, 3 splits)
    hgemm_kernel<<<dim3(II/128, 3, 2), 256, SMEM_BYTES>>>(
        ph2, wg, wu, psb0, psb1, II, DD, 704);
    red_silu_kernel<3><<<rdI, 256>>>(psb0, psb1, pa, II);
    // out[sel] = x2 + a @ w_down (K=5504, N=2048, 16 splits of 352)
    hgemm_kernel<<<dim3(DD/128, 16, 1), 256, SMEM_BYTES>>>(
        pa, wd, wd, psb0, psb0, DD, II, 352);
    copy_kernel<<<256, 256>>>((const float4*)hs, (float4*)out, (NB * DD) / 4);
    red_scatter_kernel<16><<<rdD, 256>>>(psb0, px2, out);
}